// round 11
// baseline (speedup 1.0000x reference)
#include <cuda_runtime.h>
#include <cuda_fp16.h>
#include <cstdint>

#define T_DIM 4
#define B_DIM 64
#define C_DIM 256
#define N_DIM 256
#define HEADS 8
#define TAU 0.5f
#define THRESH 1.0f
#define ATTN_THRESH 0.5f
#define BN_EPS 1e-5f
#define OROWS 512
#define TB_TOT (T_DIM * B_DIM)

// ---------------- scratch ----------------
__device__ __align__(16) int8_t g_s8[TB_TOT * N_DIM * C_DIM];   // input spikes (tb,n,c) {0,1}
__device__ __align__(16) float  g_u[TB_TOT * N_DIM * OROWS];    // q/k preacts (tb,n,o) fp32
__device__ __align__(16) int8_t g_y8[TB_TOT * N_DIM * C_DIM];   // y = attn*k (tb,n,c) {0,1}
__device__ __align__(16) int8_t g_w1d[3 * OROWS * C_DIM];       // w1 digits, plane d (LSB=0)
__device__ __align__(16) int8_t g_w2d[3 * C_DIM * C_DIM];       // w2 digits
__device__ float g_inv[OROWS], g_add[OROWS];
__device__ float g_inv2[C_DIM], g_add2[C_DIM];

// ---------------- PTX helpers ----------------
__device__ __forceinline__ uint32_t smem_u32(const void* p) {
    uint32_t a;
    asm("{ .reg .u64 t; cvta.to.shared.u64 t, %1; cvt.u32.u64 %0, t; }" : "=r"(a) : "l"(p));
    return a;
}
__device__ __forceinline__ void ldmx4(uint32_t* r, uint32_t addr) {
    asm volatile("ldmatrix.sync.aligned.m8n8.x4.shared.b16 {%0,%1,%2,%3}, [%4];"
        : "=r"(r[0]), "=r"(r[1]), "=r"(r[2]), "=r"(r[3]) : "r"(addr));
}
__device__ __forceinline__ void mma_s8(int* c, const uint32_t* a, uint32_t b0, uint32_t b1) {
    asm volatile("mma.sync.aligned.m16n8k32.row.col.s32.s8.s8.s32 "
        "{%0,%1,%2,%3}, {%4,%5,%6,%7}, {%8,%9}, {%0,%1,%2,%3};"
        : "+r"(c[0]), "+r"(c[1]), "+r"(c[2]), "+r"(c[3])
        : "r"(a[0]), "r"(a[1]), "r"(a[2]), "r"(a[3]), "r"(b0), "r"(b1));
}
__device__ __forceinline__ void cpa16(uint32_t dst, const void* src) {
    asm volatile("cp.async.cg.shared.global [%0], [%1], 16;" :: "r"(dst), "l"(src));
}
#define CPA_COMMIT() asm volatile("cp.async.commit_group;" ::: "memory")
#define CPA_WAIT(n)  asm volatile("cp.async.wait_group %0;" :: "n"(n) : "memory")

// swizzles (16B-unit granularity, conflict-free for ldmatrix)
__device__ __forceinline__ uint32_t a_off(int orow, int kb) {          // 128 x 64B chunk
    return (uint32_t)(orow * 64 + ((kb ^ ((orow >> 1) & 3)) << 4));
}
__device__ __forceinline__ uint32_t b_off(int nrow, int k16) {         // 128 x 256B resident
    return (uint32_t)(nrow * 256 + ((k16 ^ (nrow & 7)) << 4));
}

#define SMEM_G 49152   // B 32K @0 | A 2x8K @32K ; epilogue stage overlays B region

// digit scale: d=0 -> 2^-24, d=1 -> 2^-16, d=2 -> 2^-8
__device__ __forceinline__ float dscale(int d) {
    return __uint_as_float(0x33800000u + ((uint32_t)d << 26));  // +8 in exponent per digit
}

// ---------------- K0: weight digit decomposition + BN prep ----------------
__global__ void k0_prep(const float* __restrict__ wq, const float* __restrict__ wk,
                        const float* __restrict__ wp, const float* __restrict__ pb,
                        const float* __restrict__ qg, const float* __restrict__ qb,
                        const float* __restrict__ qm, const float* __restrict__ qv,
                        const float* __restrict__ kg, const float* __restrict__ kb,
                        const float* __restrict__ km, const float* __restrict__ kv,
                        const float* __restrict__ pg, const float* __restrict__ pbeta,
                        const float* __restrict__ pm, const float* __restrict__ pv) {
    int r = blockIdx.x;   // 0..767
    int c = threadIdx.x;  // 0..255
    if (r < OROWS) {
        float w = (r < C_DIM) ? wq[r * C_DIM + c] : wk[(r - C_DIM) * C_DIM + c];
        int wfix = __float2int_rn(w * 16777216.f);      // 2^24
        int d0 = (wfix << 24) >> 24;
        int r1 = (wfix - d0) >> 8;
        int d1 = (r1 << 24) >> 24;
        int d2 = (r1 - d1) >> 8;
        g_w1d[0 * OROWS * C_DIM + r * C_DIM + c] = (int8_t)d0;
        g_w1d[1 * OROWS * C_DIM + r * C_DIM + c] = (int8_t)d1;
        g_w1d[2 * OROWS * C_DIM + r * C_DIM + c] = (int8_t)d2;
        if (c == 0) {
            float iv, ad;
            if (r < C_DIM) { iv = qg[r] * rsqrtf(qv[r] + BN_EPS); ad = qb[r] - qm[r] * iv; }
            else { int o = r - C_DIM; iv = kg[o] * rsqrtf(kv[o] + BN_EPS); ad = kb[o] - km[o] * iv; }
            g_inv[r] = iv; g_add[r] = ad;
        }
    } else {
        int o = r - OROWS;
        float w = wp[o * C_DIM + c];
        int wfix = __float2int_rn(w * 16777216.f);
        int d0 = (wfix << 24) >> 24;
        int r1 = (wfix - d0) >> 8;
        int d1 = (r1 << 24) >> 24;
        int d2 = (r1 - d1) >> 8;
        g_w2d[0 * C_DIM * C_DIM + o * C_DIM + c] = (int8_t)d0;
        g_w2d[1 * C_DIM * C_DIM + o * C_DIM + c] = (int8_t)d1;
        g_w2d[2 * C_DIM * C_DIM + o * C_DIM + c] = (int8_t)d2;
        if (c == 0) {
            float iv = pg[o] * rsqrtf(pv[o] + BN_EPS);
            g_inv2[o] = iv;
            g_add2[o] = pb[o] * iv + pbeta[o] - pm[o] * iv;
        }
    }
}

// ---------------- K1: input LIF + transpose -> g_s8 (tb,n,c) bytes ----------------
__global__ __launch_bounds__(1024) void k1_lif_input(const float* __restrict__ x) {
    __shared__ float tile[T_DIM][32][33];
    const int n0 = blockIdx.x * 32, c0 = blockIdx.y * 32, b = blockIdx.z;
    const int tid = threadIdx.x;
    const int cl = tid >> 5, nl = tid & 31;
    const int cl2 = tid & 31, nl2 = tid >> 5;
    float mem = 0.f;
#pragma unroll
    for (int t = 0; t < T_DIM; t++) {
        int tb = t * B_DIM + b;
        float v = x[((size_t)tb * C_DIM + c0 + cl) * N_DIM + n0 + nl];
        mem = mem * TAU + v;
        float sp = (mem >= THRESH) ? 1.f : 0.f;
        mem *= (1.f - sp);
        tile[t][cl][nl] = sp;
    }
    __syncthreads();
#pragma unroll
    for (int t = 0; t < T_DIM; t++) {
        int tb = t * B_DIM + b;
        g_s8[((size_t)tb * N_DIM + n0 + nl2) * C_DIM + c0 + cl2] =
            (int8_t)(tile[t][cl2][nl2] != 0.f ? 1 : 0);
    }
}

// ---------------- G1: int8 digit GEMM  u = BN(W1 @ s)  M=512 N=256 K=3x256 ----------------
// grid (4 mtiles, 2 ntiles, 256 tb), 256 thr = 8 warps (4m x 2n), warp tile 32 x 64.
__global__ __launch_bounds__(256) void g1_gemm() {
    extern __shared__ char sm[];
    const uint32_t sb = smem_u32(sm);
    const uint32_t sbB = sb;
    const uint32_t sbA = sb + 32768u;
    float* stage = reinterpret_cast<float*>(sm);

    const int mtile = blockIdx.x, ntile = blockIdx.y, tb = blockIdx.z;
    const int tid = threadIdx.x, wid = tid >> 5, lane = tid & 31;
    const int warp_m = wid >> 1, warp_n = wid & 1;
    const int g = lane >> 3, rr = lane & 7;

    float accf[2][8][4];
    int accs[2][8][4];
#pragma unroll
    for (int i = 0; i < 2; i++)
#pragma unroll
        for (int j = 0; j < 8; j++)
#pragma unroll
            for (int q = 0; q < 4; q++) { accf[i][j][q] = 0.f; accs[i][j][q] = 0; }

    // B resident: 128 n-rows x 256B
    const int8_t* Bg = g_s8 + ((size_t)tb * N_DIM + ntile * 128) * C_DIM;
#pragma unroll
    for (int i = 0; i < 8; i++) {
        int idx = tid + i * 256, nrow = idx >> 4, k16 = idx & 15;
        cpa16(sbB + b_off(nrow, k16), Bg + nrow * C_DIM + k16 * 16);
    }
    CPA_COMMIT();

    const int8_t* Abase = g_w1d;
    const size_t moff = (size_t)(mtile * 128) * C_DIM;

    // issue A chunk for sequence step s (d = s>>2, ch = s&3)
#define G_ISSUE(s_) do { \
        const int8_t* Ag_ = Abase + (size_t)((s_) >> 2) * (OROWS * C_DIM) + moff + ((s_) & 3) * 64; \
        uint32_t buf_ = sbA + (uint32_t)((s_) & 1) * 8192u; \
        _Pragma("unroll") \
        for (int i_ = 0; i_ < 2; i_++) { \
            int idx_ = tid + i_ * 256, orow_ = idx_ >> 2, kb_ = idx_ & 3; \
            cpa16(buf_ + a_off(orow_, kb_), Ag_ + orow_ * C_DIM + kb_ * 16); \
        } \
        CPA_COMMIT(); \
    } while (0)

    G_ISSUE(0);
    for (int s = 0; s < 12; s++) {
        if (s + 1 < 12) { G_ISSUE(s + 1); CPA_WAIT(1); }
        else { CPA_WAIT(0); }
        __syncthreads();
        const uint32_t bufA = sbA + (uint32_t)(s & 1) * 8192u;
#pragma unroll
        for (int st = 0; st < 2; st++) {
            const int S = (s & 3) * 2 + st;   // global k32 step 0..7
            uint32_t afr[2][4];
#pragma unroll
            for (int mb = 0; mb < 2; mb++) {
                int orow = warp_m * 32 + mb * 16 + (g & 1) * 8 + rr;
                int kb = st * 2 + (g >> 1);
                ldmx4(afr[mb], bufA + a_off(orow, kb));
            }
            uint32_t bfr[8][2];
#pragma unroll
            for (int pp = 0; pp < 4; pp++) {
                int nrow = warp_n * 64 + pp * 16 + (g >> 1) * 8 + rr;
                int k16 = S * 2 + (g & 1);
                uint32_t t4[4];
                ldmx4(t4, sbB + b_off(nrow, k16));
                bfr[2 * pp][0] = t4[0]; bfr[2 * pp][1] = t4[1];
                bfr[2 * pp + 1][0] = t4[2]; bfr[2 * pp + 1][1] = t4[3];
            }
#pragma unroll
            for (int mb = 0; mb < 2; mb++)
#pragma unroll
                for (int p = 0; p < 8; p++)
                    mma_s8(accs[mb][p], afr[mb], bfr[p][0], bfr[p][1]);
        }
        __syncthreads();
        if ((s & 3) == 3) {   // digit boundary: fold into float acc, reset s32
            float dsc = dscale(s >> 2);
#pragma unroll
            for (int i = 0; i < 2; i++)
#pragma unroll
                for (int j = 0; j < 8; j++)
#pragma unroll
                    for (int q = 0; q < 4; q++) {
                        accf[i][j][q] = fmaf((float)accs[i][j][q], dsc, accf[i][j][q]);
                        accs[i][j][q] = 0;
                    }
        }
    }
#undef G_ISSUE

    // epilogue: BN + transpose via smem -> g_u (tb, n, o)
    for (int nc = 0; nc < 4; nc++) {
        if (warp_n == (nc >> 1)) {
            int nbb = (nc & 1) * 4;
#pragma unroll
            for (int mb = 0; mb < 2; mb++)
#pragma unroll
                for (int j = 0; j < 4; j++) {
                    int nb = nbb + j;
                    int o_l = warp_m * 32 + mb * 16 + (lane >> 2);
                    int nn = j * 8 + (lane & 3) * 2;
                    float iva = g_inv[mtile * 128 + o_l], ada = g_add[mtile * 128 + o_l];
                    float ivb = g_inv[mtile * 128 + o_l + 8], adb = g_add[mtile * 128 + o_l + 8];
                    stage[o_l * 33 + nn] = accf[mb][nb][0] * iva + ada;
                    stage[o_l * 33 + nn + 1] = accf[mb][nb][1] * iva + ada;
                    stage[(o_l + 8) * 33 + nn] = accf[mb][nb][2] * ivb + adb;
                    stage[(o_l + 8) * 33 + nn + 1] = accf[mb][nb][3] * ivb + adb;
                }
        }
        __syncthreads();
        {
            int n_l = tid >> 3, seg = tid & 7;
            float tmp[16];
#pragma unroll
            for (int j = 0; j < 16; j++) tmp[j] = stage[(seg * 16 + j) * 33 + n_l];
            float4* dst = reinterpret_cast<float4*>(
                g_u + ((size_t)tb * N_DIM + ntile * 128 + nc * 32 + n_l) * OROWS + mtile * 128 + seg * 16);
#pragma unroll
            for (int j = 0; j < 4; j++)
                dst[j] = make_float4(tmp[j * 4], tmp[j * 4 + 1], tmp[j * 4 + 2], tmp[j * 4 + 3]);
        }
        __syncthreads();
    }
}

// ---------------- K23 fused: LIF(u) + head sums + decay memory + attn LIF -> y bytes ----------------
__global__ __launch_bounds__(256) void k23_fused(const float* __restrict__ alpha_p) {
    const int gw = blockIdx.x * 8 + (threadIdx.x >> 5);  // (b,n)
    const int lane = threadIdx.x & 31;
    const int b = gw >> 8, n = gw & 255;
    const float a = *alpha_p;

    float memq[8], memk[8];
#pragma unroll
    for (int j = 0; j < 8; j++) { memq[j] = 0.f; memk[j] = 0.f; }
    float Ma = 0.f, Mb = 0.f, amA = 0.f, amB = 0.f;

#pragma unroll
    for (int t = 0; t < T_DIM; t++) {
        const int tb = t * B_DIM + b;
        const float4* u4 = reinterpret_cast<const float4*>(g_u + ((size_t)tb * N_DIM + n) * OROWS);
        float4 q0 = u4[lane], q1 = u4[32 + lane];
        float4 k0 = u4[64 + lane], k1 = u4[96 + lane];

        float sq[8], sk[8];
        {
            const float* qv = &q0.x;
            const float* qv1 = &q1.x;
            const float* kv = &k0.x;
            const float* kv1 = &k1.x;
#pragma unroll
            for (int j = 0; j < 4; j++) {
                float m = memq[j] * TAU + qv[j];
                sq[j] = (m >= THRESH) ? 1.f : 0.f;
                memq[j] = m * (1.f - sq[j]);
                m = memq[4 + j] * TAU + qv1[j];
                sq[4 + j] = (m >= THRESH) ? 1.f : 0.f;
                memq[4 + j] = m * (1.f - sq[4 + j]);
                m = memk[j] * TAU + kv[j];
                sk[j] = (m >= THRESH) ? 1.f : 0.f;
                memk[j] = m * (1.f - sk[j]);
                m = memk[4 + j] * TAU + kv1[j];
                sk[4 + j] = (m >= THRESH) ? 1.f : 0.f;
                memk[4 + j] = m * (1.f - sk[4 + j]);
            }
        }
        float pA = sq[0] + sq[1] + sq[2] + sq[3];
        float pB = sq[4] + sq[5] + sq[6] + sq[7];
#pragma unroll
        for (int off = 4; off > 0; off >>= 1) {
            pA += __shfl_xor_sync(0xffffffffu, pA, off, 8);
            pB += __shfl_xor_sync(0xffffffffu, pB, off, 8);
        }
        Ma = (1.f - a) * Ma + a * pA;
        float qsA = Ma + pA;
        amA = amA * TAU + qsA;
        float spA = (amA >= ATTN_THRESH) ? 1.f : 0.f;
        amA *= (1.f - spA);

        Mb = (1.f - a) * Mb + a * pB;
        float qsB = Mb + pB;
        amB = amB * TAU + qsB;
        float spB = (amB >= ATTN_THRESH) ? 1.f : 0.f;
        amB *= (1.f - spB);

        int8_t* yrow = g_y8 + ((size_t)tb * N_DIM + n) * C_DIM;
        uchar4 oA, oB;
        oA.x = (unsigned char)(sk[0] * spA); oA.y = (unsigned char)(sk[1] * spA);
        oA.z = (unsigned char)(sk[2] * spA); oA.w = (unsigned char)(sk[3] * spA);
        oB.x = (unsigned char)(sk[4] * spB); oB.y = (unsigned char)(sk[5] * spB);
        oB.z = (unsigned char)(sk[6] * spB); oB.w = (unsigned char)(sk[7] * spB);
        *reinterpret_cast<uchar4*>(yrow + 4 * lane) = oA;
        *reinterpret_cast<uchar4*>(yrow + 128 + 4 * lane) = oB;
    }
}

// ---------------- G2: int8 digit GEMM  out = BN(W2 @ y + bias)  M=256 N=256 K=3x256 ----------------
__global__ __launch_bounds__(256) void g2_gemm(float* __restrict__ out) {
    extern __shared__ char sm[];
    const uint32_t sb = smem_u32(sm);
    const uint32_t sbB = sb;
    const uint32_t sbA = sb + 32768u;

    const int mtile = blockIdx.x, ntile = blockIdx.y, tb = blockIdx.z;
    const int tid = threadIdx.x, wid = tid >> 5, lane = tid & 31;
    const int warp_m = wid >> 1, warp_n = wid & 1;
    const int g = lane >> 3, rr = lane & 7;

    float accf[2][8][4];
    int accs[2][8][4];
#pragma unroll
    for (int i = 0; i < 2; i++)
#pragma unroll
        for (int j = 0; j < 8; j++)
#pragma unroll
            for (int q = 0; q < 4; q++) { accf[i][j][q] = 0.f; accs[i][j][q] = 0; }

    const int8_t* Bg = g_y8 + ((size_t)tb * N_DIM + ntile * 128) * C_DIM;
#pragma unroll
    for (int i = 0; i < 8; i++) {
        int idx = tid + i * 256, nrow = idx >> 4, k16 = idx & 15;
        cpa16(sbB + b_off(nrow, k16), Bg + nrow * C_DIM + k16 * 16);
    }
    CPA_COMMIT();

    const int8_t* Abase = g_w2d;
    const size_t moff = (size_t)(mtile * 128) * C_DIM;

#define G_ISSUE(s_) do { \
        const int8_t* Ag_ = Abase + (size_t)((s_) >> 2) * (C_DIM * C_DIM) + moff + ((s_) & 3) * 64; \
        uint32_t buf_ = sbA + (uint32_t)((s_) & 1) * 8192u; \
        _Pragma("unroll") \
        for (int i_ = 0; i_ < 2; i_++) { \
            int idx_ = tid + i_ * 256, orow_ = idx_ >> 2, kb_ = idx_ & 3; \
            cpa16(buf_ + a_off(orow_, kb_), Ag_ + orow_ * C_DIM + kb_ * 16); \
        } \
        CPA_COMMIT(); \
    } while (0)

    G_ISSUE(0);
    for (int s = 0; s < 12; s++) {
        if (s + 1 < 12) { G_ISSUE(s + 1); CPA_WAIT(1); }
        else { CPA_WAIT(0); }
        __syncthreads();
        const uint32_t bufA = sbA + (uint32_t)(s & 1) * 8192u;
#pragma unroll
        for (int st = 0; st < 2; st++) {
            const int S = (s & 3) * 2 + st;
            uint32_t afr[2][4];
#pragma unroll
            for (int mb = 0; mb < 2; mb++) {
                int orow = warp_m * 32 + mb * 16 + (g & 1) * 8 + rr;
                int kb = st * 2 + (g >> 1);
                ldmx4(afr[mb], bufA + a_off(orow, kb));
            }
            uint32_t bfr[8][2];
#pragma unroll
            for (int pp = 0; pp < 4; pp++) {
                int nrow = warp_n * 64 + pp * 16 + (g >> 1) * 8 + rr;
                int k16 = S * 2 + (g & 1);
                uint32_t t4[4];
                ldmx4(t4, sbB + b_off(nrow, k16));
                bfr[2 * pp][0] = t4[0]; bfr[2 * pp][1] = t4[1];
                bfr[2 * pp + 1][0] = t4[2]; bfr[2 * pp + 1][1] = t4[3];
            }
#pragma unroll
            for (int mb = 0; mb < 2; mb++)
#pragma unroll
                for (int p = 0; p < 8; p++)
                    mma_s8(accs[mb][p], afr[mb], bfr[p][0], bfr[p][1]);
        }
        __syncthreads();
        if ((s & 3) == 3) {
            float dsc = dscale(s >> 2);
#pragma unroll
            for (int i = 0; i < 2; i++)
#pragma unroll
                for (int j = 0; j < 8; j++)
#pragma unroll
                    for (int q = 0; q < 4; q++) {
                        accf[i][j][q] = fmaf((float)accs[i][j][q], dsc, accf[i][j][q]);
                        accs[i][j][q] = 0;
                    }
        }
    }
#undef G_ISSUE

    // epilogue: BN + bias, direct store (tb, o, n)
#pragma unroll
    for (int mb = 0; mb < 2; mb++) {
        int o0 = mtile * 128 + warp_m * 32 + mb * 16 + (lane >> 2);
        float iva = g_inv2[o0], ada = g_add2[o0];
        float ivb = g_inv2[o0 + 8], adb = g_add2[o0 + 8];
#pragma unroll
        for (int nb = 0; nb < 8; nb++) {
            int n_g = ntile * 128 + warp_n * 64 + nb * 8 + (lane & 3) * 2;
            float2 v0 = make_float2(accf[mb][nb][0] * iva + ada, accf[mb][nb][1] * iva + ada);
            float2 v1 = make_float2(accf[mb][nb][2] * ivb + adb, accf[mb][nb][3] * ivb + adb);
            *reinterpret_cast<float2*>(out + ((size_t)tb * C_DIM + o0) * N_DIM + n_g) = v0;
            *reinterpret_cast<float2*>(out + ((size_t)tb * C_DIM + o0 + 8) * N_DIM + n_g) = v1;
        }
    }
}

// ---------------- launch ----------------
extern "C" void kernel_launch(void* const* d_in, const int* in_sizes, int n_in,
                              void* d_out, int out_size) {
    const float* x       = (const float*)d_in[0];
    const float* q_w     = (const float*)d_in[1];
    const float* q_gamma = (const float*)d_in[2];
    const float* q_beta  = (const float*)d_in[3];
    const float* q_mean  = (const float*)d_in[4];
    const float* q_var   = (const float*)d_in[5];
    const float* k_w     = (const float*)d_in[6];
    const float* k_gamma = (const float*)d_in[7];
    const float* k_beta  = (const float*)d_in[8];
    const float* k_mean  = (const float*)d_in[9];
    const float* k_var   = (const float*)d_in[10];
    const float* proj_w  = (const float*)d_in[11];
    const float* proj_b  = (const float*)d_in[12];
    const float* proj_g  = (const float*)d_in[13];
    const float* proj_be = (const float*)d_in[14];
    const float* proj_m  = (const float*)d_in[15];
    const float* proj_v  = (const float*)d_in[16];
    const float* alpha   = (const float*)d_in[17];
    float* out = (float*)d_out;

    cudaFuncSetAttribute(g1_gemm, cudaFuncAttributeMaxDynamicSharedMemorySize, SMEM_G);
    cudaFuncSetAttribute(g2_gemm, cudaFuncAttributeMaxDynamicSharedMemorySize, SMEM_G);

    k0_prep<<<OROWS + C_DIM, 256>>>(q_w, k_w, proj_w, proj_b,
                                    q_gamma, q_beta, q_mean, q_var,
                                    k_gamma, k_beta, k_mean, k_var,
                                    proj_g, proj_be, proj_m, proj_v);
    {
        dim3 grid(N_DIM / 32, C_DIM / 32, B_DIM);
        k1_lif_input<<<grid, 1024>>>(x);
    }
    {
        dim3 grid(4, 2, TB_TOT);
        g1_gemm<<<grid, 256, SMEM_G>>>();
    }
    {
        k23_fused<<<B_DIM * N_DIM / 8, 256>>>(alpha);
    }
    {
        dim3 grid(2, 2, TB_TOT);
        g2_gemm<<<grid, 256, SMEM_G>>>(out);
    }
}

// round 12
// speedup vs baseline: 1.2378x; 1.2378x over previous
#include <cuda_runtime.h>
#include <cuda_fp16.h>
#include <cstdint>

#define T_DIM 4
#define B_DIM 64
#define C_DIM 256
#define N_DIM 256
#define HEADS 8
#define TAU 0.5f
#define THRESH 1.0f
#define ATTN_THRESH 0.5f
#define BN_EPS 1e-5f
#define OROWS 512
#define TB_TOT (T_DIM * B_DIM)
#define LO_SCALE 0.00048828125f   // 2^-11, exact power of two

#define SW128(b) ((b) ^ (((b) >> 3) & 0x70))

// ---------------- scratch ----------------
// g_s interleaved-K: column 2c = spike, 2c+1 = spike*2^-11 (pairs w1's hi/lo digits)
__device__ __align__(16) __half g_s[TB_TOT * N_DIM * 512];     // [tb][n][2c|2c+1]
__device__ __align__(16) float  g_u[TB_TOT * N_DIM * OROWS];   // preacts (tb,n,o) fp32
__device__ __align__(16) __half g_y[TB_TOT * N_DIM * C_DIM];   // y = attn*k (tb,n,c) plain fp16
__device__ __align__(16) __half g_w1[OROWS * 512];             // [o][hi,lo interleaved]
__device__ __align__(16) __half g_w2h[C_DIM * C_DIM];          // [o][c] fp16(w2) (hi only)
__device__ float g_inv[OROWS], g_add[OROWS];
__device__ float g_inv2[C_DIM], g_add2[C_DIM];

// ---------------- PTX helpers ----------------
__device__ __forceinline__ uint32_t smem_u32(const void* p) {
    uint32_t a;
    asm("{ .reg .u64 t; cvta.to.shared.u64 t, %1; cvt.u32.u64 %0, t; }" : "=r"(a) : "l"(p));
    return a;
}
__device__ __forceinline__ void ldmx4(uint32_t* r, uint32_t addr) {
    asm volatile("ldmatrix.sync.aligned.m8n8.x4.shared.b16 {%0,%1,%2,%3}, [%4];"
        : "=r"(r[0]), "=r"(r[1]), "=r"(r[2]), "=r"(r[3]) : "r"(addr));
}
__device__ __forceinline__ void mma16816(float* c, const uint32_t* a, uint32_t b0, uint32_t b1) {
    asm volatile("mma.sync.aligned.m16n8k16.row.col.f32.f16.f16.f32 "
        "{%0,%1,%2,%3}, {%4,%5,%6,%7}, {%8,%9}, {%0,%1,%2,%3};"
        : "+f"(c[0]), "+f"(c[1]), "+f"(c[2]), "+f"(c[3])
        : "r"(a[0]), "r"(a[1]), "r"(a[2]), "r"(a[3]), "r"(b0), "r"(b1));
}
__device__ __forceinline__ void cpa16(uint32_t dst, const void* src) {
    asm volatile("cp.async.cg.shared.global [%0], [%1], 16;" :: "r"(dst), "l"(src));
}
#define CPA_COMMIT() asm volatile("cp.async.commit_group;" ::: "memory")
#define CPA_WAIT(n)  asm volatile("cp.async.wait_group %0;" :: "n"(n) : "memory")

// ---------------- K0: weight prep (w1 split interleaved, w2 hi-only) + BN ----------------
__global__ void k0_prep(const float* __restrict__ wq, const float* __restrict__ wk,
                        const float* __restrict__ wp, const float* __restrict__ pb,
                        const float* __restrict__ qg, const float* __restrict__ qb,
                        const float* __restrict__ qm, const float* __restrict__ qv,
                        const float* __restrict__ kg, const float* __restrict__ kb,
                        const float* __restrict__ km, const float* __restrict__ kv,
                        const float* __restrict__ pg, const float* __restrict__ pbeta,
                        const float* __restrict__ pm, const float* __restrict__ pv) {
    int r = blockIdx.x;   // 0..767
    int c = threadIdx.x;  // 0..255
    if (r < OROWS) {
        float w = (r < C_DIM) ? wq[r * C_DIM + c] : wk[(r - C_DIM) * C_DIM + c];
        __half hi = __float2half_rn(w);
        float lo = (w - __half2float(hi)) * 2048.f;
        g_w1[r * 512 + 2 * c] = hi;
        g_w1[r * 512 + 2 * c + 1] = __float2half_rn(lo);
        if (c == 0) {
            float iv, ad;
            if (r < C_DIM) { iv = qg[r] * rsqrtf(qv[r] + BN_EPS); ad = qb[r] - qm[r] * iv; }
            else { int o = r - C_DIM; iv = kg[o] * rsqrtf(kv[o] + BN_EPS); ad = kb[o] - km[o] * iv; }
            g_inv[r] = iv; g_add[r] = ad;
        }
    } else {
        int o = r - OROWS;
        g_w2h[o * C_DIM + c] = __float2half_rn(wp[o * C_DIM + c]);
        if (c == 0) {
            float iv = pg[o] * rsqrtf(pv[o] + BN_EPS);
            g_inv2[o] = iv;
            g_add2[o] = pb[o] * iv + pbeta[o] - pm[o] * iv;
        }
    }
}

// ---------------- K1: input LIF + transpose -> g_s (tb,n,interleaved c) ----------------
__global__ __launch_bounds__(1024) void k1_lif_input(const float* __restrict__ x) {
    __shared__ float tile[T_DIM][32][33];
    const int n0 = blockIdx.x * 32, c0 = blockIdx.y * 32, b = blockIdx.z;
    const int tid = threadIdx.x;
    const int cl = tid >> 5, nl = tid & 31;
    const int cl2 = tid & 31, nl2 = tid >> 5;
    float mem = 0.f;
#pragma unroll
    for (int t = 0; t < T_DIM; t++) {
        int tb = t * B_DIM + b;
        float v = x[((size_t)tb * C_DIM + c0 + cl) * N_DIM + n0 + nl];
        mem = mem * TAU + v;
        float sp = (mem >= THRESH) ? 1.f : 0.f;
        mem *= (1.f - sp);
        tile[t][cl][nl] = sp;
    }
    __syncthreads();
#pragma unroll
    for (int t = 0; t < T_DIM; t++) {
        int tb = t * B_DIM + b;
        float s2 = tile[t][cl2][nl2];
        size_t base = ((size_t)tb * N_DIM + n0 + nl2) * 512 + 2 * (c0 + cl2);
        *reinterpret_cast<__half2*>(g_s + base) = __floats2half2_rn(s2, s2 * LO_SCALE);
    }
}

// ---------------- G1: GEMM u = BN(W1 @ s), 2-stage cp.async  M=512 N=256 K=512 ----------------
__global__ __launch_bounds__(256) void g1_gemm() {
    extern __shared__ char sm[];
    float* stage = reinterpret_cast<float*>(sm);
    const uint32_t sb = smem_u32(sm);

    const int mtile = blockIdx.x, ntile = blockIdx.y, tb = blockIdx.z;
    const int tid = threadIdx.x, wid = tid >> 5, lane = tid & 31;
    const int warp_m = wid >> 1, warp_n = wid & 1;

    float acc[2][8][4];
#pragma unroll
    for (int i = 0; i < 2; i++)
#pragma unroll
        for (int j = 0; j < 8; j++)
#pragma unroll
            for (int q = 0; q < 4; q++) acc[i][j][q] = 0.f;

    const int a_row = warp_m * 32 + (lane & 7) + ((lane >> 3) & 1) * 8;
    const int a_kadd = (lane >> 4) * 8;
    const int b_row = warp_n * 64 + (lane & 7) + (lane >> 4) * 8;
    const int b_kadd = ((lane >> 3) & 1) * 8;

    const __half* Ag = g_w1 + (size_t)(mtile * 128) * 512;
    const __half* Bg = g_s + ((size_t)tb * N_DIM + ntile * 128) * 512;

#pragma unroll
    for (int i = 0; i < 4; i++) {
        int idx = tid + i * 256, row = idx >> 3, c16 = idx & 7;
        cpa16(sb + SW128(row * 128 + c16 * 16), Ag + row * 512 + c16 * 8);
        cpa16(sb + 32768u + SW128(row * 128 + c16 * 16), Bg + row * 512 + c16 * 8);
    }
    CPA_COMMIT();

    for (int ch = 0; ch < 8; ch++) {
        const uint32_t bufA = sb + (uint32_t)(ch & 1) * 16384u;
        const uint32_t bufB = sb + 32768u + (uint32_t)(ch & 1) * 16384u;
        if (ch < 7) {
            const int kc = (ch + 1) * 64;
            const uint32_t nA = sb + (uint32_t)((ch + 1) & 1) * 16384u;
            const uint32_t nB = sb + 32768u + (uint32_t)((ch + 1) & 1) * 16384u;
#pragma unroll
            for (int i = 0; i < 4; i++) {
                int idx = tid + i * 256, row = idx >> 3, c16 = idx & 7;
                cpa16(nA + SW128(row * 128 + c16 * 16), Ag + row * 512 + kc + c16 * 8);
                cpa16(nB + SW128(row * 128 + c16 * 16), Bg + row * 512 + kc + c16 * 8);
            }
            CPA_COMMIT();
            CPA_WAIT(1);
        } else {
            CPA_WAIT(0);
        }
        __syncthreads();
#pragma unroll
        for (int k16 = 0; k16 < 4; k16++) {
            uint32_t afr[2][4], bfr[4][4];
#pragma unroll
            for (int mb = 0; mb < 2; mb++)
                ldmx4(afr[mb], bufA + SW128((a_row + mb * 16) * 128 + (k16 * 16 + a_kadd) * 2));
#pragma unroll
            for (int p = 0; p < 4; p++)
                ldmx4(bfr[p], bufB + SW128((b_row + p * 16) * 128 + (k16 * 16 + b_kadd) * 2));
#pragma unroll
            for (int mb = 0; mb < 2; mb++)
#pragma unroll
                for (int p = 0; p < 4; p++) {
                    mma16816(acc[mb][2 * p], afr[mb], bfr[p][0], bfr[p][1]);
                    mma16816(acc[mb][2 * p + 1], afr[mb], bfr[p][2], bfr[p][3]);
                }
        }
        __syncthreads();
    }

    // epilogue: BN + transpose via smem -> g_u (tb, n, o)
    for (int nc = 0; nc < 4; nc++) {
        if (warp_n == (nc >> 1)) {
            int nbb = (nc & 1) * 4;
#pragma unroll
            for (int mb = 0; mb < 2; mb++)
#pragma unroll
                for (int j = 0; j < 4; j++) {
                    int nb = nbb + j;
                    int o_l = warp_m * 32 + mb * 16 + (lane >> 2);
                    int nn = j * 8 + (lane & 3) * 2;
                    float iva = g_inv[mtile * 128 + o_l], ada = g_add[mtile * 128 + o_l];
                    float ivb = g_inv[mtile * 128 + o_l + 8], adb = g_add[mtile * 128 + o_l + 8];
                    stage[o_l * 33 + nn] = acc[mb][nb][0] * iva + ada;
                    stage[o_l * 33 + nn + 1] = acc[mb][nb][1] * iva + ada;
                    stage[(o_l + 8) * 33 + nn] = acc[mb][nb][2] * ivb + adb;
                    stage[(o_l + 8) * 33 + nn + 1] = acc[mb][nb][3] * ivb + adb;
                }
        }
        __syncthreads();
        {
            int n_l = tid >> 3, seg = tid & 7;
            float tmp[16];
#pragma unroll
            for (int j = 0; j < 16; j++) tmp[j] = stage[(seg * 16 + j) * 33 + n_l];
            float4* dst = reinterpret_cast<float4*>(
                g_u + ((size_t)tb * N_DIM + ntile * 128 + nc * 32 + n_l) * OROWS + mtile * 128 + seg * 16);
#pragma unroll
            for (int j = 0; j < 4; j++)
                dst[j] = make_float4(tmp[j * 4], tmp[j * 4 + 1], tmp[j * 4 + 2], tmp[j * 4 + 3]);
        }
        __syncthreads();
    }
}

// ---------------- K23 fused: LIF(u) + head sums + decay memory + attn LIF -> y fp16 ----------------
__global__ __launch_bounds__(256) void k23_fused(const float* __restrict__ alpha_p) {
    const int gw = blockIdx.x * 8 + (threadIdx.x >> 5);  // (b,n)
    const int lane = threadIdx.x & 31;
    const int b = gw >> 8, n = gw & 255;
    const float a = *alpha_p;

    float memq[8], memk[8];
#pragma unroll
    for (int j = 0; j < 8; j++) { memq[j] = 0.f; memk[j] = 0.f; }
    float Ma = 0.f, Mb = 0.f, amA = 0.f, amB = 0.f;

#pragma unroll
    for (int t = 0; t < T_DIM; t++) {
        const int tb = t * B_DIM + b;
        const float4* u4 = reinterpret_cast<const float4*>(g_u + ((size_t)tb * N_DIM + n) * OROWS);
        float4 q0 = u4[lane], q1 = u4[32 + lane];
        float4 k0 = u4[64 + lane], k1 = u4[96 + lane];

        float sq[8], sk[8];
        {
            const float* qv = &q0.x;
            const float* qv1 = &q1.x;
            const float* kv = &k0.x;
            const float* kv1 = &k1.x;
#pragma unroll
            for (int j = 0; j < 4; j++) {
                float m = memq[j] * TAU + qv[j];
                sq[j] = (m >= THRESH) ? 1.f : 0.f;
                memq[j] = m * (1.f - sq[j]);
                m = memq[4 + j] * TAU + qv1[j];
                sq[4 + j] = (m >= THRESH) ? 1.f : 0.f;
                memq[4 + j] = m * (1.f - sq[4 + j]);
                m = memk[j] * TAU + kv[j];
                sk[j] = (m >= THRESH) ? 1.f : 0.f;
                memk[j] = m * (1.f - sk[j]);
                m = memk[4 + j] * TAU + kv1[j];
                sk[4 + j] = (m >= THRESH) ? 1.f : 0.f;
                memk[4 + j] = m * (1.f - sk[4 + j]);
            }
        }
        float pA = sq[0] + sq[1] + sq[2] + sq[3];
        float pB = sq[4] + sq[5] + sq[6] + sq[7];
#pragma unroll
        for (int off = 4; off > 0; off >>= 1) {
            pA += __shfl_xor_sync(0xffffffffu, pA, off, 8);
            pB += __shfl_xor_sync(0xffffffffu, pB, off, 8);
        }
        Ma = (1.f - a) * Ma + a * pA;
        float qsA = Ma + pA;
        amA = amA * TAU + qsA;
        float spA = (amA >= ATTN_THRESH) ? 1.f : 0.f;
        amA *= (1.f - spA);

        Mb = (1.f - a) * Mb + a * pB;
        float qsB = Mb + pB;
        amB = amB * TAU + qsB;
        float spB = (amB >= ATTN_THRESH) ? 1.f : 0.f;
        amB *= (1.f - spB);

        // y = attn * k  -> plain fp16 (tb,n,c); lane owns c {4l..4l+3} and {128+4l..}
        __half* yrow = g_y + ((size_t)tb * N_DIM + n) * C_DIM;
        uint2 oA, oB;
        __half2* hA = reinterpret_cast<__half2*>(&oA);
        __half2* hB = reinterpret_cast<__half2*>(&oB);
        hA[0] = __floats2half2_rn(sk[0] * spA, sk[1] * spA);
        hA[1] = __floats2half2_rn(sk[2] * spA, sk[3] * spA);
        hB[0] = __floats2half2_rn(sk[4] * spB, sk[5] * spB);
        hB[1] = __floats2half2_rn(sk[6] * spB, sk[7] * spB);
        *reinterpret_cast<uint2*>(yrow + 4 * lane) = oA;
        *reinterpret_cast<uint2*>(yrow + 128 + 4 * lane) = oB;
    }
}

// ---------------- G2: GEMM out = BN(W2h @ y + bias), 2-stage  M=256 N=256 K=256 ----------------
__global__ __launch_bounds__(256) void g2_gemm(float* __restrict__ out) {
    extern __shared__ char sm[];
    const uint32_t sb = smem_u32(sm);

    const int mtile = blockIdx.x, ntile = blockIdx.y, tb = blockIdx.z;
    const int tid = threadIdx.x, wid = tid >> 5, lane = tid & 31;
    const int warp_m = wid >> 1, warp_n = wid & 1;

    float acc[2][8][4];
#pragma unroll
    for (int i = 0; i < 2; i++)
#pragma unroll
        for (int j = 0; j < 8; j++)
#pragma unroll
            for (int q = 0; q < 4; q++) acc[i][j][q] = 0.f;

    const int a_row = warp_m * 32 + (lane & 7) + ((lane >> 3) & 1) * 8;
    const int a_kadd = (lane >> 4) * 8;
    const int b_row = warp_n * 64 + (lane & 7) + (lane >> 4) * 8;
    const int b_kadd = ((lane >> 3) & 1) * 8;

    const __half* Ag = g_w2h + (size_t)(mtile * 128) * C_DIM;
    const __half* Bg = g_y + ((size_t)tb * N_DIM + ntile * 128) * C_DIM;

#pragma unroll
    for (int i = 0; i < 4; i++) {
        int idx = tid + i * 256, row = idx >> 3, c16 = idx & 7;
        cpa16(sb + SW128(row * 128 + c16 * 16), Ag + row * C_DIM + c16 * 8);
        cpa16(sb + 32768u + SW128(row * 128 + c16 * 16), Bg + row * C_DIM + c16 * 8);
    }
    CPA_COMMIT();

    for (int ch = 0; ch < 4; ch++) {
        const uint32_t bufA = sb + (uint32_t)(ch & 1) * 16384u;
        const uint32_t bufB = sb + 32768u + (uint32_t)(ch & 1) * 16384u;
        if (ch < 3) {
            const int kc = (ch + 1) * 64;
            const uint32_t nA = sb + (uint32_t)((ch + 1) & 1) * 16384u;
            const uint32_t nB = sb + 32768u + (uint32_t)((ch + 1) & 1) * 16384u;
#pragma unroll
            for (int i = 0; i < 4; i++) {
                int idx = tid + i * 256, row = idx >> 3, c16 = idx & 7;
                cpa16(nA + SW128(row * 128 + c16 * 16), Ag + row * C_DIM + kc + c16 * 8);
                cpa16(nB + SW128(row * 128 + c16 * 16), Bg + row * C_DIM + kc + c16 * 8);
            }
            CPA_COMMIT();
            CPA_WAIT(1);
        } else {
            CPA_WAIT(0);
        }
        __syncthreads();
#pragma unroll
        for (int k16 = 0; k16 < 4; k16++) {
            uint32_t afr[2][4], bfr[4][4];
#pragma unroll
            for (int mb = 0; mb < 2; mb++)
                ldmx4(afr[mb], bufA + SW128((a_row + mb * 16) * 128 + (k16 * 16 + a_kadd) * 2));
#pragma unroll
            for (int p = 0; p < 4; p++)
                ldmx4(bfr[p], bufB + SW128((b_row + p * 16) * 128 + (k16 * 16 + b_kadd) * 2));
#pragma unroll
            for (int mb = 0; mb < 2; mb++)
#pragma unroll
                for (int p = 0; p < 4; p++) {
                    mma16816(acc[mb][2 * p], afr[mb], bfr[p][0], bfr[p][1]);
                    mma16816(acc[mb][2 * p + 1], afr[mb], bfr[p][2], bfr[p][3]);
                }
        }
        __syncthreads();
    }

    // epilogue: BN + bias, direct store to out (tb, o, n)
#pragma unroll
    for (int mb = 0; mb < 2; mb++) {
        int o0 = mtile * 128 + warp_m * 32 + mb * 16 + (lane >> 2);
        float iva = g_inv2[o0], ada = g_add2[o0];
        float ivb = g_inv2[o0 + 8], adb = g_add2[o0 + 8];
#pragma unroll
        for (int nb = 0; nb < 8; nb++) {
            int n_g = ntile * 128 + warp_n * 64 + nb * 8 + (lane & 3) * 2;
            float2 v0 = make_float2(acc[mb][nb][0] * iva + ada, acc[mb][nb][1] * iva + ada);
            float2 v1 = make_float2(acc[mb][nb][2] * ivb + adb, acc[mb][nb][3] * ivb + adb);
            *reinterpret_cast<float2*>(out + ((size_t)tb * C_DIM + o0) * N_DIM + n_g) = v0;
            *reinterpret_cast<float2*>(out + ((size_t)tb * C_DIM + o0 + 8) * N_DIM + n_g) = v1;
        }
    }
}

// ---------------- launch ----------------
extern "C" void kernel_launch(void* const* d_in, const int* in_sizes, int n_in,
                              void* d_out, int out_size) {
    const float* x       = (const float*)d_in[0];
    const float* q_w     = (const float*)d_in[1];
    const float* q_gamma = (const float*)d_in[2];
    const float* q_beta  = (const float*)d_in[3];
    const float* q_mean  = (const float*)d_in[4];
    const float* q_var   = (const float*)d_in[5];
    const float* k_w     = (const float*)d_in[6];
    const float* k_gamma = (const float*)d_in[7];
    const float* k_beta  = (const float*)d_in[8];
    const float* k_mean  = (const float*)d_in[9];
    const float* k_var   = (const float*)d_in[10];
    const float* proj_w  = (const float*)d_in[11];
    const float* proj_b  = (const float*)d_in[12];
    const float* proj_g  = (const float*)d_in[13];
    const float* proj_be = (const float*)d_in[14];
    const float* proj_m  = (const float*)d_in[15];
    const float* proj_v  = (const float*)d_in[16];
    const float* alpha   = (const float*)d_in[17];
    float* out = (float*)d_out;

    cudaFuncSetAttribute(g1_gemm, cudaFuncAttributeMaxDynamicSharedMemorySize, 65536);
    cudaFuncSetAttribute(g2_gemm, cudaFuncAttributeMaxDynamicSharedMemorySize, 65536);

    k0_prep<<<OROWS + C_DIM, 256>>>(q_w, k_w, proj_w, proj_b,
                                    q_gamma, q_beta, q_mean, q_var,
                                    k_gamma, k_beta, k_mean, k_var,
                                    proj_g, proj_be, proj_m, proj_v);
    {
        dim3 grid(N_DIM / 32, C_DIM / 32, B_DIM);
        k1_lif_input<<<grid, 1024>>>(x);
    }
    {
        dim3 grid(4, 2, TB_TOT);
        g1_gemm<<<grid, 256, 65536>>>();
    }
    {
        k23_fused<<<B_DIM * N_DIM / 8, 256>>>(alpha);
    }
    {
        dim3 grid(2, 2, TB_TOT);
        g2_gemm<<<grid, 256, 65536>>>(out);
    }
}